// round 14
// baseline (speedup 1.0000x reference)
#include <cuda_runtime.h>
#include <cuda_bf16.h>
#include <math.h>
#include <stdint.h>

#define Bb 4
#define Ss 2048
#define Dd 1024
#define Hh 16
#define Mm 4

#define BMSD (4LL*4*2048*1024)
#define BSD  (4LL*2048*1024)

static const int h_dims[4] = {768, 1024, 512, 2048};
static const int h_sls[4]  = {2048, 1024, 1500, 512};
static const long long h_xoff[4] = {0, 6291456, 10485760, 13557760};
#define XTOT 17752064
static const long long h_woff[8] = {0, 786432, 1835008, 2359296, 4456448, 5505024, 6553600, 7602176};
#define WTOT 8650752

// ---------------- scratch (device globals) -----------------------------------
__device__ __nv_bfloat16 g_xhi[XTOT], g_xlo[XTOT];
__device__ __nv_bfloat16 g_whi[WTOT], g_wlo[WTOT];
__device__ __nv_bfloat16 g_shi[BMSD], g_slo[BMSD];
__device__ float g_Q[BMSD], g_K[BMSD], g_V[BMSD];
__device__ __nv_bfloat16 g_fhi[BSD], g_flo[BSD];

// Cantor routes (exact-double semantics): coords = [0, 0, 0.5, 0.99609375]
__constant__ int c_routes[4][3] = {{0, 1, 2}, {0, 1, 2}, {2, 3, 0}, {3, 2, 0}};
__constant__ int c_sl[4] = {2048, 1024, 1500, 512};

// ---------------- helpers -----------------------------------------------------
__device__ __forceinline__ uint32_t smem_u32(const void* p) {
    uint32_t a;
    asm("{ .reg .u64 t; cvta.to.shared.u64 t, %1; cvt.u32.u64 %0, t; }" : "=r"(a) : "l"(p));
    return a;
}

#define CPA(sa, ga, sz) \
    asm volatile("cp.async.cg.shared.global [%0], [%1], 16, %2;" \
                 :: "r"(sa), "l"(ga), "r"(sz) : "memory")
#define CPA_COMMIT() asm volatile("cp.async.commit_group;" ::: "memory")
#define CPA_WAIT1()  asm volatile("cp.async.wait_group 1;" ::: "memory")

#define LDSM4(r0, r1, r2, r3, addr) \
    asm volatile("ldmatrix.sync.aligned.m8n8.x4.shared.b16 {%0,%1,%2,%3}, [%4];" \
                 : "=r"(r0), "=r"(r1), "=r"(r2), "=r"(r3) : "r"(addr))

#define MMA16816(d, a, b) \
    asm volatile("mma.sync.aligned.m16n8k16.row.col.f32.bf16.bf16.f32 " \
                 "{%0,%1,%2,%3}, {%4,%5,%6,%7}, {%8,%9}, {%0,%1,%2,%3};" \
                 : "+f"((d)[0]), "+f"((d)[1]), "+f"((d)[2]), "+f"((d)[3]) \
                 : "r"((a)[0]), "r"((a)[1]), "r"((a)[2]), "r"((a)[3]), \
                   "r"((b)[0]), "r"((b)[1]))

// ---------------- merged bf16 hi/lo split (12 segments, one launch) ----------
struct SplitSegs {
    const float* src[12];
    __nv_bfloat16* hi[12];
    __nv_bfloat16* lo[12];
    long long start[13];
};

__global__ void split_all_kernel(SplitSegs segs) {
    long long total = segs.start[12];
    for (long long i = (long long)blockIdx.x * blockDim.x + threadIdx.x; i < total;
         i += (long long)gridDim.x * blockDim.x) {
        int seg = 0;
#pragma unroll
        for (int s = 1; s < 12; s++) seg += (i >= segs.start[s]) ? 1 : 0;
        long long local = i - segs.start[seg];
        float x = segs.src[seg][local];
        __nv_bfloat16 h = __float2bfloat16(x);
        segs.hi[seg][local] = h;
        segs.lo[seg][local] = __float2bfloat16(x - __bfloat162float(h));
    }
}

// ---------------- bf16x2 mma.sync GEMM: C = A @ W^T (+bias,+bias2) -----------
// Block tile 128x256, 256 threads (8 warps = 2M x 4N, warp tile 64x64), BK=32,
// 3-stage cp.async ring, one __syncthreads per iteration.
#define PITCHB 80
#define A_SZ (128 * PITCHB)         // 10240
#define B_SZ (256 * PITCHB)         // 20480
#define STAGE_SZ (2 * A_SZ + 2 * B_SZ)  // 61440
#define GEMM_SMEM (3 * STAGE_SZ)        // 184320

__global__ void __launch_bounds__(256, 1) gemm_bf16x2(
    const __nv_bfloat16* __restrict__ Ahi, const __nv_bfloat16* __restrict__ Alo,
    int lda,
    const __nv_bfloat16* __restrict__ Bhi, const __nv_bfloat16* __restrict__ Blo,
    const float* __restrict__ bias, const float* __restrict__ bias2,
    float* __restrict__ Cp, __nv_bfloat16* __restrict__ Chi, __nv_bfloat16* __restrict__ Clo,
    int Mrows, int K, int liveMode, int c_slv, long long c_outer, long long c_modoff)
{
    extern __shared__ char smem[];
    const uint32_t sbase = smem_u32(smem);
    int tid = threadIdx.x, wid = tid >> 5, lane = tid & 31;
    int warp_m = wid & 1, warp_n = wid >> 1;    // 2 x 4
    int bm = blockIdx.y * 128, bn = blockIdx.x * 256;

    if (liveMode && ((bm & 2047) >= c_sl[(bm >> 11) & 3])) return;

    // ---- A load slots: 2 per thread per array (128 rows x 4 chunks) ----
    uint32_t aoffs[2]; long long abyte[2]; uint32_t aszv[2];
#pragma unroll
    for (int j = 0; j < 2; j++) {
        int rem = tid + j * 256;          // [0,512)
        int row = rem >> 2, ch = rem & 3;
        aoffs[j] = (uint32_t)(row * PITCHB + ch * 16);
        int gr = bm + row;
        bool av = (gr < Mrows) && (!liveMode || ((gr & 2047) < c_sl[(gr >> 11) & 3]));
        aszv[j] = av ? 16u : 0u;
        abyte[j] = av ? ((long long)gr * lda + ch * 8) * 2 : 0;
    }
    // ---- B load slots: 4 per thread per array (256 rows x 4 chunks) ----
    uint32_t boffs[4]; long long bbyte[4];
#pragma unroll
    for (int j = 0; j < 4; j++) {
        int rem = tid + j * 256;          // [0,1024)
        int row = rem >> 2, ch = rem & 3;
        boffs[j] = (uint32_t)(row * PITCHB + ch * 16);
        bbyte[j] = ((long long)(bn + row) * K + ch * 8) * 2;
    }

    const int NK = K >> 5;

    auto issue = [&](int kt2) {
        uint32_t st = sbase + (uint32_t)(kt2 % 3) * STAGE_SZ;
        long long kb = (long long)kt2 * 64;
#pragma unroll
        for (int j = 0; j < 2; j++) {
            CPA(st + aoffs[j],        (const char*)Ahi + abyte[j] + kb, aszv[j]);
            CPA(st + A_SZ + aoffs[j], (const char*)Alo + abyte[j] + kb, aszv[j]);
        }
#pragma unroll
        for (int j = 0; j < 4; j++) {
            CPA(st + 2 * A_SZ + boffs[j],        (const char*)Bhi + bbyte[j] + kb, 16u);
            CPA(st + 2 * A_SZ + B_SZ + boffs[j], (const char*)Blo + bbyte[j] + kb, 16u);
        }
    };

    issue(0); CPA_COMMIT();
    issue(1); CPA_COMMIT();

    float acc[4][8][4];
#pragma unroll
    for (int a = 0; a < 4; a++)
#pragma unroll
        for (int b = 0; b < 8; b++)
#pragma unroll
            for (int c = 0; c < 4; c++) acc[a][b][c] = 0.f;

    int lrow = lane & 7, lsel = lane >> 3;
    int arow0 = warp_m * 64 + ((lsel & 1) << 3) + lrow;
    int brow0 = warp_n * 64 + ((lsel & 1) << 3) + lrow;
    int colp  = (lsel >> 1) << 3;

    for (int kt = 0; kt < NK; ++kt) {
        CPA_WAIT1();
        __syncthreads();
        if (kt + 2 < NK) issue(kt + 2);
        CPA_COMMIT();

        uint32_t st = sbase + (uint32_t)(kt % 3) * STAGE_SZ;
        uint32_t aH = st, aL = st + A_SZ, bH = st + 2 * A_SZ, bL = st + 2 * A_SZ + B_SZ;

#pragma unroll
        for (int ks = 0; ks < 2; ks++) {
            int c0 = ks * 16;
            uint32_t ah[4][4], al[4][4], bh[8][2], bl[8][2];
#pragma unroll
            for (int mi = 0; mi < 4; mi++) {
                uint32_t off = (uint32_t)((arow0 + mi * 16) * PITCHB + (colp + c0) * 2);
                LDSM4(ah[mi][0], ah[mi][1], ah[mi][2], ah[mi][3], aH + off);
                LDSM4(al[mi][0], al[mi][1], al[mi][2], al[mi][3], aL + off);
            }
#pragma unroll
            for (int nj = 0; nj < 4; nj++) {
                uint32_t off = (uint32_t)((brow0 + nj * 16) * PITCHB + (colp + c0) * 2);
                uint32_t t0, t1, t2, t3;
                LDSM4(t0, t1, t2, t3, bH + off);
                bh[nj * 2 + 0][0] = t0; bh[nj * 2 + 0][1] = t2;
                bh[nj * 2 + 1][0] = t1; bh[nj * 2 + 1][1] = t3;
                LDSM4(t0, t1, t2, t3, bL + off);
                bl[nj * 2 + 0][0] = t0; bl[nj * 2 + 0][1] = t2;
                bl[nj * 2 + 1][0] = t1; bl[nj * 2 + 1][1] = t3;
            }
#pragma unroll
            for (int mi = 0; mi < 4; mi++)
#pragma unroll
                for (int ni = 0; ni < 8; ni++) {
                    MMA16816(acc[mi][ni], ah[mi], bh[ni]);
                    MMA16816(acc[mi][ni], ah[mi], bl[ni]);
                    MMA16816(acc[mi][ni], al[mi], bh[ni]);
                }
        }
    }

    // ---- epilogue ----
    int q = lane >> 2, i2 = (lane & 3) * 2;
#pragma unroll
    for (int mi = 0; mi < 4; mi++) {
        int r0 = bm + warp_m * 64 + mi * 16 + q;
        int r1 = r0 + 8;
        bool ok0 = (r0 < Mrows) && (!liveMode || ((r0 & 2047) < c_sl[(r0 >> 11) & 3]));
        bool ok1 = (r1 < Mrows) && (!liveMode || ((r1 & 2047) < c_sl[(r1 >> 11) & 3]));
        long long o0 = ok0 ? (long long)(r0 / c_slv) * c_outer + c_modoff +
                             (long long)(r0 % c_slv) * 1024 : 0;
        long long o1 = ok1 ? (long long)(r1 / c_slv) * c_outer + c_modoff +
                             (long long)(r1 % c_slv) * 1024 : 0;
#pragma unroll
        for (int ni = 0; ni < 8; ni++) {
            int c = bn + warp_n * 64 + ni * 8 + i2;
#pragma unroll
            for (int e = 0; e < 2; e++) {
                int col = c + e;
                float bsum = bias[col] + (bias2 ? bias2[col] : 0.f);
                if (ok0) {
                    float v = acc[mi][ni][e] + bsum;
                    if (Chi) {
                        __nv_bfloat16 h = __float2bfloat16(v);
                        Chi[o0 + col] = h;
                        Clo[o0 + col] = __float2bfloat16(v - __bfloat162float(h));
                    } else Cp[o0 + col] = v;
                }
                if (ok1) {
                    float v = acc[mi][ni][2 + e] + bsum;
                    if (Chi) {
                        __nv_bfloat16 h = __float2bfloat16(v);
                        Chi[o1 + col] = h;
                        Clo[o1 + col] = __float2bfloat16(v - __bfloat162float(h));
                    } else Cp[o1 + col] = v;
                }
            }
        }
    }
}

// ---------------- fused routed attention + mean, pad rows = bias -------------
__global__ void __launch_bounds__(128) attn_fuse_kernel(
    const float* __restrict__ tptr, const float* __restrict__ bq,
    const float* __restrict__ bk, const float* __restrict__ bv)
{
    int s = blockIdx.x;
    int b = blockIdx.z;
    int h = blockIdx.y * 4 + (threadIdx.x >> 5);
    int lane = threadIdx.x & 31;

    float invscale = 1.f / (8.f * fabsf(*tptr));

    int col = h * 64 + lane;
    long long base = ((long long)b * Mm) * Ss * Dd + (long long)s * Dd + col;

    float q0[4], q1[4], k0[4], k1[4], v0[4], v1[4];
#pragma unroll
    for (int m = 0; m < 4; m++) {
        bool live = s < c_sl[m];
        long long idx = base + (long long)m * Ss * Dd;
        q0[m] = live ? g_Q[idx]      : bq[col];
        q1[m] = live ? g_Q[idx + 32] : bq[col + 32];
        k0[m] = live ? g_K[idx]      : bk[col];
        k1[m] = live ? g_K[idx + 32] : bk[col + 32];
        v0[m] = live ? g_V[idx]      : bv[col];
        v1[m] = live ? g_V[idx + 32] : bv[col + 32];
    }

    float acc0 = 0.f, acc1 = 0.f;
#pragma unroll
    for (int m = 0; m < 4; m++) {
        float sc[3];
#pragma unroll
        for (int w = 0; w < 3; w++) {
            int r = c_routes[m][w];
            float p = q0[m] * k0[r] + q1[m] * k1[r];
#pragma unroll
            for (int o = 16; o > 0; o >>= 1) p += __shfl_xor_sync(0xffffffffu, p, o);
            sc[w] = p * invscale;
        }
        float mx = fmaxf(sc[0], fmaxf(sc[1], sc[2]));
        float e0 = expf(sc[0] - mx), e1 = expf(sc[1] - mx), e2 = expf(sc[2] - mx);
        float inv = 1.f / (e0 + e1 + e2);
        e0 *= inv; e1 *= inv; e2 *= inv;
        int r0 = c_routes[m][0], r1 = c_routes[m][1], r2 = c_routes[m][2];
        acc0 += e0 * v0[r0] + e1 * v0[r1] + e2 * v0[r2];
        acc1 += e0 * v1[r0] + e1 * v1[r1] + e2 * v1[r2];
    }

    long long fidx = ((long long)b * Ss + s) * Dd + col;
    float f0 = acc0 * 0.25f, f1 = acc1 * 0.25f;
    __nv_bfloat16 h0 = __float2bfloat16(f0), h1 = __float2bfloat16(f1);
    g_fhi[fidx]      = h0;  g_flo[fidx]      = __float2bfloat16(f0 - __bfloat162float(h0));
    g_fhi[fidx + 32] = h1;  g_flo[fidx + 32] = __float2bfloat16(f1 - __bfloat162float(h1));
}

// ---------------- host launcher ----------------------------------------------
extern "C" void kernel_launch(void* const* d_in, const int* in_sizes, int n_in,
                              void* d_out, int out_size)
{
    bool dictOrder = (in_sizes[1] == 1024 * 768);
    int xi[4], wi[4], bi[4];
    if (dictOrder) {
        int x[4] = {0, 3, 6, 9}, w[4] = {1, 4, 7, 10}, bb[4] = {2, 5, 8, 11};
        for (int i = 0; i < 4; i++) { xi[i] = x[i]; wi[i] = w[i]; bi[i] = bb[i]; }
    } else {
        int x[4] = {0, 1, 2, 3}, w[4] = {4, 6, 8, 10}, bb[4] = {5, 7, 9, 11};
        for (int i = 0; i < 4; i++) { xi[i] = x[i]; wi[i] = w[i]; bi[i] = bb[i]; }
    }
    const float* X[4]; const float* Wmod[4]; const float* bmod[4];
    for (int i = 0; i < 4; i++) {
        X[i]    = (const float*)d_in[xi[i]];
        Wmod[i] = (const float*)d_in[wi[i]];
        bmod[i] = (const float*)d_in[bi[i]];
    }
    const float* mod_emb = (const float*)d_in[12];
    const float* Wq = (const float*)d_in[13]; const float* bq = (const float*)d_in[14];
    const float* Wk = (const float*)d_in[15]; const float* bk = (const float*)d_in[16];
    const float* Wv = (const float*)d_in[17]; const float* bv = (const float*)d_in[18];
    const float* Wo = (const float*)d_in[19]; const float* bo = (const float*)d_in[20];
    const float* tptr = (const float*)d_in[21];

    __nv_bfloat16 *xhi, *xlo, *whi, *wlo, *shi, *slo, *fhi, *flo;
    float *Qb, *Kb, *Vb;
    cudaGetSymbolAddress((void**)&xhi, g_xhi);  cudaGetSymbolAddress((void**)&xlo, g_xlo);
    cudaGetSymbolAddress((void**)&whi, g_whi);  cudaGetSymbolAddress((void**)&wlo, g_wlo);
    cudaGetSymbolAddress((void**)&shi, g_shi);  cudaGetSymbolAddress((void**)&slo, g_slo);
    cudaGetSymbolAddress((void**)&Qb, g_Q);     cudaGetSymbolAddress((void**)&Kb, g_K);
    cudaGetSymbolAddress((void**)&Vb, g_V);
    cudaGetSymbolAddress((void**)&fhi, g_fhi);  cudaGetSymbolAddress((void**)&flo, g_flo);

    cudaFuncSetAttribute(gemm_bf16x2, cudaFuncAttributeMaxDynamicSharedMemorySize, GEMM_SMEM);

    // 1) all bf16 hi/lo splits in ONE launch
    {
        SplitSegs segs;
        long long cum = 0;
        for (int i = 0; i < 4; i++) {
            segs.src[i] = X[i];
            segs.hi[i] = xhi + h_xoff[i];
            segs.lo[i] = xlo + h_xoff[i];
            segs.start[i] = cum;
            cum += (long long)Bb * h_sls[i] * h_dims[i];
        }
        const float* Wall[8] = {Wmod[0], Wmod[1], Wmod[2], Wmod[3], Wq, Wk, Wv, Wo};
        for (int i = 0; i < 8; i++) {
            segs.src[4 + i] = Wall[i];
            segs.hi[4 + i] = whi + h_woff[i];
            segs.lo[4 + i] = wlo + h_woff[i];
            segs.start[4 + i] = cum;
            cum += (i < 4) ? (long long)1024 * h_dims[i] : 1024LL * 1024;
        }
        segs.start[12] = cum;
        split_all_kernel<<<2048, 256>>>(segs);
    }

    // 2) modality projections -> stacked (bf16 hi/lo)
    for (int i = 0; i < 4; i++) {
        int Mr = Bb * h_sls[i];
        dim3 grid(4, (Mr + 127) / 128);
        gemm_bf16x2<<<grid, 256, GEMM_SMEM>>>(
            xhi + h_xoff[i], xlo + h_xoff[i], h_dims[i],
            whi + h_woff[i], wlo + h_woff[i], bmod[i], mod_emb + (long long)i * 1024,
            nullptr, shi, slo,
            Mr, h_dims[i], 0, h_sls[i], (long long)Mm * Ss * Dd, (long long)i * Ss * Dd);
    }

    // 3) QKV projections: one full-range launch per tensor, modality liveness
    float* QKV[3] = {Qb, Kb, Vb};
    const float* bqkv[3] = {bq, bk, bv};
    for (int t = 0; t < 3; t++) {
        dim3 grid(4, (Bb * Mm * Ss) / 128);
        gemm_bf16x2<<<grid, 256, GEMM_SMEM>>>(
            shi, slo, 1024,
            whi + h_woff[4 + t], wlo + h_woff[4 + t], bqkv[t], nullptr,
            QKV[t], nullptr, nullptr,
            Bb * Mm * Ss, 1024, 1, 1 << 30, 0LL, 0LL);
    }

    // 4) fused routed attention + modality mean -> fused (bf16 hi/lo)
    {
        dim3 grid(Ss, Hh / 4, Bb);
        attn_fuse_kernel<<<grid, 128>>>(tptr, bq, bk, bv);
    }

    // 5) output projection: out = fused @ Wo^T + bo -> f32 d_out
    {
        int Mr = Bb * Ss;
        dim3 grid(4, Mr / 128);
        gemm_bf16x2<<<grid, 256, GEMM_SMEM>>>(
            fhi, flo, 1024,
            whi + h_woff[7], wlo + h_woff[7], bo, nullptr,
            (float*)d_out, nullptr, nullptr,
            Mr, 1024, 0, 1 << 30, 0LL, 0LL);
    }
}

// round 16
// speedup vs baseline: 1.1403x; 1.1403x over previous
#include <cuda_runtime.h>
#include <cuda_bf16.h>
#include <math.h>
#include <stdint.h>

#define Bb 4
#define Ss 2048
#define Dd 1024
#define Hh 16
#define Mm 4

#define BMSD (4LL*4*2048*1024)
#define BSD  (4LL*2048*1024)

static const int h_dims[4] = {768, 1024, 512, 2048};
static const int h_sls[4]  = {2048, 1024, 1500, 512};
static const long long h_xoff[4] = {0, 6291456, 10485760, 13557760};
#define XTOT 17752064
static const long long h_woff[8] = {0, 786432, 1835008, 2359296, 4456448, 5505024, 6553600, 7602176};
#define WTOT 8650752

// ---------------- scratch (device globals) -----------------------------------
__device__ __nv_bfloat16 g_xhi[XTOT], g_xlo[XTOT];
__device__ __nv_bfloat16 g_whi[WTOT], g_wlo[WTOT];
__device__ __nv_bfloat16 g_shi[BMSD], g_slo[BMSD];
__device__ float g_Q[BMSD], g_K[BMSD], g_V[BMSD];
__device__ __nv_bfloat16 g_fhi[BSD], g_flo[BSD];

// Cantor routes (exact-double semantics): coords = [0, 0, 0.5, 0.99609375]
__constant__ int c_routes[4][3] = {{0, 1, 2}, {0, 1, 2}, {2, 3, 0}, {3, 2, 0}};
__constant__ int c_sl[4] = {2048, 1024, 1500, 512};

// ---------------- helpers -----------------------------------------------------
__device__ __forceinline__ uint32_t smem_u32(const void* p) {
    uint32_t a;
    asm("{ .reg .u64 t; cvta.to.shared.u64 t, %1; cvt.u32.u64 %0, t; }" : "=r"(a) : "l"(p));
    return a;
}

#define CPA(sa, ga, sz) \
    asm volatile("cp.async.cg.shared.global [%0], [%1], 16, %2;" \
                 :: "r"(sa), "l"(ga), "r"(sz) : "memory")
#define CPA_COMMIT() asm volatile("cp.async.commit_group;" ::: "memory")
#define CPA_WAIT1()  asm volatile("cp.async.wait_group 1;" ::: "memory")

#define LDSM4(r0, r1, r2, r3, addr) \
    asm volatile("ldmatrix.sync.aligned.m8n8.x4.shared.b16 {%0,%1,%2,%3}, [%4];" \
                 : "=r"(r0), "=r"(r1), "=r"(r2), "=r"(r3) : "r"(addr))

#define MMA16816(d, a, b) \
    asm volatile("mma.sync.aligned.m16n8k16.row.col.f32.bf16.bf16.f32 " \
                 "{%0,%1,%2,%3}, {%4,%5,%6,%7}, {%8,%9}, {%0,%1,%2,%3};" \
                 : "+f"((d)[0]), "+f"((d)[1]), "+f"((d)[2]), "+f"((d)[3]) \
                 : "r"((a)[0]), "r"((a)[1]), "r"((a)[2]), "r"((a)[3]), \
                   "r"((b)[0]), "r"((b)[1]))

// ---------------- merged bf16 hi/lo split (12 segments, one launch) ----------
struct SplitSegs {
    const float* src[12];
    __nv_bfloat16* hi[12];
    __nv_bfloat16* lo[12];
    long long start[13];
};

__global__ void split_all_kernel(SplitSegs segs) {
    long long total = segs.start[12];
    for (long long i = (long long)blockIdx.x * blockDim.x + threadIdx.x; i < total;
         i += (long long)gridDim.x * blockDim.x) {
        int seg = 0;
#pragma unroll
        for (int s = 1; s < 12; s++) seg += (i >= segs.start[s]) ? 1 : 0;
        long long local = i - segs.start[seg];
        float x = segs.src[seg][local];
        __nv_bfloat16 h = __float2bfloat16(x);
        segs.hi[seg][local] = h;
        segs.lo[seg][local] = __float2bfloat16(x - __bfloat162float(h));
    }
}

// ---------------- bf16x2 mma.sync GEMM: C = A @ W^T (+bias,+bias2) -----------
// Block tile 128x128, 256 threads (8 warps, warp tile 64x32), BK=32,
// 2-stage cp.async ring (80KB SMEM) so TWO CTAs co-reside per SM.
#define PITCHB 80
#define ASZ (128 * PITCHB)          // 10240 per array
#define STAGE_SZ (4 * ASZ)          // Ah, Al, Bh, Bl = 40960
#define GEMM_SMEM (2 * STAGE_SZ)    // 81920 -> 2 CTAs/SM

__global__ void __launch_bounds__(256, 2) gemm_bf16x2(
    const __nv_bfloat16* __restrict__ Ahi, const __nv_bfloat16* __restrict__ Alo,
    int lda,
    const __nv_bfloat16* __restrict__ Bhi, const __nv_bfloat16* __restrict__ Blo,
    const float* __restrict__ bias, const float* __restrict__ bias2,
    float* __restrict__ Cp, __nv_bfloat16* __restrict__ Chi, __nv_bfloat16* __restrict__ Clo,
    int Mrows, int K, int liveMode, int c_slv, long long c_outer, long long c_modoff)
{
    extern __shared__ char smem[];
    const uint32_t sbase = smem_u32(smem);
    int tid = threadIdx.x, wid = tid >> 5, lane = tid & 31;
    int warp_m = wid & 1, warp_n = wid >> 1;
    int bm = blockIdx.y * 128, bn = blockIdx.x * 128;

    if (liveMode && ((bm & 2047) >= c_sl[(bm >> 11) & 3])) return;

    // ---- load slots: 2 per thread per array (128 rows x 4 chunks of 16B) ----
    uint32_t smoff[2];
    long long abyte[2], bbyte[2];
    uint32_t asz[2];
#pragma unroll
    for (int i = 0; i < 2; i++) {
        int s = tid + i * 256;
        int row = s >> 2, ch = s & 3;
        smoff[i] = (uint32_t)(row * PITCHB + ch * 16);
        int gr = bm + row;
        bool av = (gr < Mrows) && (!liveMode || ((gr & 2047) < c_sl[(gr >> 11) & 3]));
        asz[i] = av ? 16u : 0u;
        abyte[i] = av ? ((long long)gr * lda + ch * 8) * 2 : 0;
        bbyte[i] = ((long long)(bn + row) * K + ch * 8) * 2;
    }

    const int NK = K >> 5;

    auto issue = [&](int kt2) {
        uint32_t st = sbase + (uint32_t)(kt2 & 1) * STAGE_SZ;
        long long kb = (long long)kt2 * 64;
#pragma unroll
        for (int i = 0; i < 2; i++) {
            CPA(st + 0 * ASZ + smoff[i], (const char*)Ahi + abyte[i] + kb, asz[i]);
            CPA(st + 1 * ASZ + smoff[i], (const char*)Alo + abyte[i] + kb, asz[i]);
            CPA(st + 2 * ASZ + smoff[i], (const char*)Bhi + bbyte[i] + kb, 16u);
            CPA(st + 3 * ASZ + smoff[i], (const char*)Blo + bbyte[i] + kb, 16u);
        }
    };

    issue(0); CPA_COMMIT();
    issue(1); CPA_COMMIT();

    float acc[4][4][4];
#pragma unroll
    for (int a = 0; a < 4; a++)
#pragma unroll
        for (int b = 0; b < 4; b++)
#pragma unroll
            for (int c = 0; c < 4; c++) acc[a][b][c] = 0.f;

    int lrow = lane & 7, lsel = lane >> 3;
    int arow0 = warp_m * 64 + ((lsel & 1) << 3) + lrow;
    int brow0 = warp_n * 32 + ((lsel & 1) << 3) + lrow;
    int colp  = (lsel >> 1) << 3;

    for (int kt = 0; kt < NK; ++kt) {
        CPA_WAIT1();
        __syncthreads();

        uint32_t st = sbase + (uint32_t)(kt & 1) * STAGE_SZ;
        uint32_t aH = st, aL = st + ASZ, bH = st + 2 * ASZ, bL = st + 3 * ASZ;

#pragma unroll
        for (int ks = 0; ks < 2; ks++) {
            int c0 = ks * 16;
            uint32_t ah[4][4], al[4][4], bh[4][2], bl[4][2];
#pragma unroll
            for (int mi = 0; mi < 4; mi++) {
                uint32_t off = (uint32_t)((arow0 + mi * 16) * PITCHB + (colp + c0) * 2);
                LDSM4(ah[mi][0], ah[mi][1], ah[mi][2], ah[mi][3], aH + off);
                LDSM4(al[mi][0], al[mi][1], al[mi][2], al[mi][3], aL + off);
            }
#pragma unroll
            for (int nj = 0; nj < 2; nj++) {
                uint32_t off = (uint32_t)((brow0 + nj * 16) * PITCHB + (colp + c0) * 2);
                uint32_t t0, t1, t2, t3;
                LDSM4(t0, t1, t2, t3, bH + off);
                bh[nj * 2 + 0][0] = t0; bh[nj * 2 + 0][1] = t2;
                bh[nj * 2 + 1][0] = t1; bh[nj * 2 + 1][1] = t3;
                LDSM4(t0, t1, t2, t3, bL + off);
                bl[nj * 2 + 0][0] = t0; bl[nj * 2 + 0][1] = t2;
                bl[nj * 2 + 1][0] = t1; bl[nj * 2 + 1][1] = t3;
            }
#pragma unroll
            for (int mi = 0; mi < 4; mi++)
#pragma unroll
                for (int ni = 0; ni < 4; ni++) {
                    MMA16816(acc[mi][ni], ah[mi], bh[ni]);
                    MMA16816(acc[mi][ni], ah[mi], bl[ni]);
                    MMA16816(acc[mi][ni], al[mi], bh[ni]);
                }
        }
        __syncthreads();
        if (kt + 2 < NK) issue(kt + 2);
        CPA_COMMIT();
    }

    // ---- epilogue ----
    int q = lane >> 2, i2 = (lane & 3) * 2;
#pragma unroll
    for (int mi = 0; mi < 4; mi++) {
        int r0 = bm + warp_m * 64 + mi * 16 + q;
        int r1 = r0 + 8;
        bool ok0 = (r0 < Mrows) && (!liveMode || ((r0 & 2047) < c_sl[(r0 >> 11) & 3]));
        bool ok1 = (r1 < Mrows) && (!liveMode || ((r1 & 2047) < c_sl[(r1 >> 11) & 3]));
        long long o0 = ok0 ? (long long)(r0 / c_slv) * c_outer + c_modoff +
                             (long long)(r0 % c_slv) * 1024 : 0;
        long long o1 = ok1 ? (long long)(r1 / c_slv) * c_outer + c_modoff +
                             (long long)(r1 % c_slv) * 1024 : 0;
#pragma unroll
        for (int ni = 0; ni < 4; ni++) {
            int c = bn + warp_n * 32 + ni * 8 + i2;
#pragma unroll
            for (int e = 0; e < 2; e++) {
                int col = c + e;
                float bsum = bias[col] + (bias2 ? bias2[col] : 0.f);
                if (ok0) {
                    float v = acc[mi][ni][e] + bsum;
                    if (Chi) {
                        __nv_bfloat16 h = __float2bfloat16(v);
                        Chi[o0 + col] = h;
                        Clo[o0 + col] = __float2bfloat16(v - __bfloat162float(h));
                    } else Cp[o0 + col] = v;
                }
                if (ok1) {
                    float v = acc[mi][ni][2 + e] + bsum;
                    if (Chi) {
                        __nv_bfloat16 h = __float2bfloat16(v);
                        Chi[o1 + col] = h;
                        Clo[o1 + col] = __float2bfloat16(v - __bfloat162float(h));
                    } else Cp[o1 + col] = v;
                }
            }
        }
    }
}

// ---------------- fused routed attention + mean, pad rows = bias -------------
__global__ void __launch_bounds__(128) attn_fuse_kernel(
    const float* __restrict__ tptr, const float* __restrict__ bq,
    const float* __restrict__ bk, const float* __restrict__ bv)
{
    int s = blockIdx.x;
    int b = blockIdx.z;
    int h = blockIdx.y * 4 + (threadIdx.x >> 5);
    int lane = threadIdx.x & 31;

    float invscale = 1.f / (8.f * fabsf(*tptr));

    int col = h * 64 + lane;
    long long base = ((long long)b * Mm) * Ss * Dd + (long long)s * Dd + col;

    float q0[4], q1[4], k0[4], k1[4], v0[4], v1[4];
#pragma unroll
    for (int m = 0; m < 4; m++) {
        bool live = s < c_sl[m];
        long long idx = base + (long long)m * Ss * Dd;
        q0[m] = live ? g_Q[idx]      : bq[col];
        q1[m] = live ? g_Q[idx + 32] : bq[col + 32];
        k0[m] = live ? g_K[idx]      : bk[col];
        k1[m] = live ? g_K[idx + 32] : bk[col + 32];
        v0[m] = live ? g_V[idx]      : bv[col];
        v1[m] = live ? g_V[idx + 32] : bv[col + 32];
    }

    float acc0 = 0.f, acc1 = 0.f;
#pragma unroll
    for (int m = 0; m < 4; m++) {
        float sc[3];
#pragma unroll
        for (int w = 0; w < 3; w++) {
            int r = c_routes[m][w];
            float p = q0[m] * k0[r] + q1[m] * k1[r];
#pragma unroll
            for (int o = 16; o > 0; o >>= 1) p += __shfl_xor_sync(0xffffffffu, p, o);
            sc[w] = p * invscale;
        }
        float mx = fmaxf(sc[0], fmaxf(sc[1], sc[2]));
        float e0 = expf(sc[0] - mx), e1 = expf(sc[1] - mx), e2 = expf(sc[2] - mx);
        float inv = 1.f / (e0 + e1 + e2);
        e0 *= inv; e1 *= inv; e2 *= inv;
        int r0 = c_routes[m][0], r1 = c_routes[m][1], r2 = c_routes[m][2];
        acc0 += e0 * v0[r0] + e1 * v0[r1] + e2 * v0[r2];
        acc1 += e0 * v1[r0] + e1 * v1[r1] + e2 * v1[r2];
    }

    long long fidx = ((long long)b * Ss + s) * Dd + col;
    float f0 = acc0 * 0.25f, f1 = acc1 * 0.25f;
    __nv_bfloat16 h0 = __float2bfloat16(f0), h1 = __float2bfloat16(f1);
    g_fhi[fidx]      = h0;  g_flo[fidx]      = __float2bfloat16(f0 - __bfloat162float(h0));
    g_fhi[fidx + 32] = h1;  g_flo[fidx + 32] = __float2bfloat16(f1 - __bfloat162float(h1));
}

// ---------------- host launcher ----------------------------------------------
extern "C" void kernel_launch(void* const* d_in, const int* in_sizes, int n_in,
                              void* d_out, int out_size)
{
    bool dictOrder = (in_sizes[1] == 1024 * 768);
    int xi[4], wi[4], bi[4];
    if (dictOrder) {
        int x[4] = {0, 3, 6, 9}, w[4] = {1, 4, 7, 10}, bb[4] = {2, 5, 8, 11};
        for (int i = 0; i < 4; i++) { xi[i] = x[i]; wi[i] = w[i]; bi[i] = bb[i]; }
    } else {
        int x[4] = {0, 1, 2, 3}, w[4] = {4, 6, 8, 10}, bb[4] = {5, 7, 9, 11};
        for (int i = 0; i < 4; i++) { xi[i] = x[i]; wi[i] = w[i]; bi[i] = bb[i]; }
    }
    const float* X[4]; const float* Wmod[4]; const float* bmod[4];
    for (int i = 0; i < 4; i++) {
        X[i]    = (const float*)d_in[xi[i]];
        Wmod[i] = (const float*)d_in[wi[i]];
        bmod[i] = (const float*)d_in[bi[i]];
    }
    const float* mod_emb = (const float*)d_in[12];
    const float* Wq = (const float*)d_in[13]; const float* bq = (const float*)d_in[14];
    const float* Wk = (const float*)d_in[15]; const float* bk = (const float*)d_in[16];
    const float* Wv = (const float*)d_in[17]; const float* bv = (const float*)d_in[18];
    const float* Wo = (const float*)d_in[19]; const float* bo = (const float*)d_in[20];
    const float* tptr = (const float*)d_in[21];

    __nv_bfloat16 *xhi, *xlo, *whi, *wlo, *shi, *slo, *fhi, *flo;
    float *Qb, *Kb, *Vb;
    cudaGetSymbolAddress((void**)&xhi, g_xhi);  cudaGetSymbolAddress((void**)&xlo, g_xlo);
    cudaGetSymbolAddress((void**)&whi, g_whi);  cudaGetSymbolAddress((void**)&wlo, g_wlo);
    cudaGetSymbolAddress((void**)&shi, g_shi);  cudaGetSymbolAddress((void**)&slo, g_slo);
    cudaGetSymbolAddress((void**)&Qb, g_Q);     cudaGetSymbolAddress((void**)&Kb, g_K);
    cudaGetSymbolAddress((void**)&Vb, g_V);
    cudaGetSymbolAddress((void**)&fhi, g_fhi);  cudaGetSymbolAddress((void**)&flo, g_flo);

    cudaFuncSetAttribute(gemm_bf16x2, cudaFuncAttributeMaxDynamicSharedMemorySize, GEMM_SMEM);

    // 1) all bf16 hi/lo splits in ONE launch
    {
        SplitSegs segs;
        long long cum = 0;
        for (int i = 0; i < 4; i++) {
            segs.src[i] = X[i];
            segs.hi[i] = xhi + h_xoff[i];
            segs.lo[i] = xlo + h_xoff[i];
            segs.start[i] = cum;
            cum += (long long)Bb * h_sls[i] * h_dims[i];
        }
        const float* Wall[8] = {Wmod[0], Wmod[1], Wmod[2], Wmod[3], Wq, Wk, Wv, Wo};
        for (int i = 0; i < 8; i++) {
            segs.src[4 + i] = Wall[i];
            segs.hi[4 + i] = whi + h_woff[i];
            segs.lo[4 + i] = wlo + h_woff[i];
            segs.start[4 + i] = cum;
            cum += (i < 4) ? (long long)1024 * h_dims[i] : 1024LL * 1024;
        }
        segs.start[12] = cum;
        split_all_kernel<<<2048, 256>>>(segs);
    }

    // 2) modality projections -> stacked (bf16 hi/lo)
    for (int i = 0; i < 4; i++) {
        int Mr = Bb * h_sls[i];
        dim3 grid(8, (Mr + 127) / 128);
        gemm_bf16x2<<<grid, 256, GEMM_SMEM>>>(
            xhi + h_xoff[i], xlo + h_xoff[i], h_dims[i],
            whi + h_woff[i], wlo + h_woff[i], bmod[i], mod_emb + (long long)i * 1024,
            nullptr, shi, slo,
            Mr, h_dims[i], 0, h_sls[i], (long long)Mm * Ss * Dd, (long long)i * Ss * Dd);
    }

    // 3) QKV projections: one full-range launch per tensor, modality liveness
    float* QKV[3] = {Qb, Kb, Vb};
    const float* bqkv[3] = {bq, bk, bv};
    for (int t = 0; t < 3; t++) {
        dim3 grid(8, (Bb * Mm * Ss) / 128);
        gemm_bf16x2<<<grid, 256, GEMM_SMEM>>>(
            shi, slo, 1024,
            whi + h_woff[4 + t], wlo + h_woff[4 + t], bqkv[t], nullptr,
            QKV[t], nullptr, nullptr,
            Bb * Mm * Ss, 1024, 1, 1 << 30, 0LL, 0LL);
    }

    // 4) fused routed attention + modality mean -> fused (bf16 hi/lo)
    {
        dim3 grid(Ss, Hh / 4, Bb);
        attn_fuse_kernel<<<grid, 128>>>(tptr, bq, bk, bv);
    }

    // 5) output projection: out = fused @ Wo^T + bo -> f32 d_out
    {
        int Mr = Bb * Ss;
        dim3 grid(8, Mr / 128);
        gemm_bf16x2<<<grid, 256, GEMM_SMEM>>>(
            fhi, flo, 1024,
            whi + h_woff[7], wlo + h_woff[7], bo, nullptr,
            (float*)d_out, nullptr, nullptr,
            Mr, 1024, 0, 1 << 30, 0LL, 0LL);
    }
}